// round 14
// baseline (speedup 1.0000x reference)
#include <cuda_runtime.h>
#include <cuda_fp16.h>
#include <cstdint>

#define N_NODES 50000
#define N_EDGES 1600000
#define NODE_DIMV 3
#define HID 128
#define N_GRAPHS 512
#define N_HEADSV 5

#define TILES_PER_BLOCK 20
#define NBLK (N_EDGES / (64 * TILES_PER_BLOCK))   // 1250

// dynamic smem layout for k_fused5
#define OFF_BS   0        // __half [256][40]  = 20480 B
#define OFF_AS   20480    // __half [64][40]   = 5120 B
#define OFF_SMF  25600    // __half [64][132]  = 16896 B
#define OFF_SMS  42496    // __half [64][132]  = 16896 B
#define SMEM_FUSED 59392

// ---------------- device scratch ----------------
__device__ float  g_h1[N_NODES * NODE_DIMV];      // conv1 output
__device__ float  g_acc2[N_NODES * HID];          // conv2 accumulator (init = h2)
__device__ float  g_acc3[N_NODES * HID];          // conv3 accumulator (init = relu(acc2))
__device__ __half g_P[N_NODES * 512];             // node proj table: [fd|sd|fs|ss] per node
__device__ float  g_gsum[N_GRAPHS * HID];
__device__ float  g_cnt[N_GRAPHS];
// dst-sort scratch + materialized sorted edge data (fp16)
__device__ int    g_hist[N_NODES];
__device__ int    g_off[N_NODES];
__device__ int    g_fill[N_NODES];
__device__ __half g_eas[(size_t)N_EDGES * 32];    // edge attrs, dst-sorted, fp16
__device__ int    g_srcs[N_EDGES];                // src in sorted order
__device__ int    g_dsts[N_EDGES];                // dst in sorted order

// ---------------- helpers ----------------
__device__ __forceinline__ float sigf(float v) {
    float z = __expf(-v);
    return __fdividef(1.0f, 1.0f + z);
}
__device__ __forceinline__ float spf(float v) {
    float a = fabsf(v);
    float t = __expf(-a);
    return fmaxf(v, 0.0f) + __logf(1.0f + t);
}
__device__ __forceinline__ void red4(float* p, float a, float b, float c, float d) {
    asm volatile("red.global.add.v4.f32 [%0], {%1,%2,%3,%4};"
                 :: "l"(p), "f"(a), "f"(b), "f"(c), "f"(d) : "memory");
}
__device__ __forceinline__ uint32_t to_tf32(float v) {
    uint32_t r; asm("cvt.rna.tf32.f32 %0, %1;" : "=r"(r) : "f"(v)); return r;
}
__device__ __forceinline__ void mma_tf32(float c[4], const uint32_t a[4], const uint32_t b[2]) {
    asm volatile(
        "mma.sync.aligned.m16n8k8.row.col.f32.tf32.tf32.f32 "
        "{%0,%1,%2,%3},{%4,%5,%6,%7},{%8,%9},{%0,%1,%2,%3};"
        : "+f"(c[0]), "+f"(c[1]), "+f"(c[2]), "+f"(c[3])
        : "r"(a[0]), "r"(a[1]), "r"(a[2]), "r"(a[3]), "r"(b[0]), "r"(b[1]));
}
__device__ __forceinline__ void mma_f16(float c[4], const uint32_t a[4], const uint32_t b[2]) {
    asm volatile(
        "mma.sync.aligned.m16n8k16.row.col.f32.f16.f16.f32 "
        "{%0,%1,%2,%3},{%4,%5,%6,%7},{%8,%9},{%0,%1,%2,%3};"
        : "+f"(c[0]), "+f"(c[1]), "+f"(c[2]), "+f"(c[3])
        : "r"(a[0]), "r"(a[1]), "r"(a[2]), "r"(a[3]), "r"(b[0]), "r"(b[1]));
}
__device__ __forceinline__ float4 ldh4(const __half* p) {
    uint2 u = *reinterpret_cast<const uint2*>(p);
    __half2 a = *reinterpret_cast<__half2*>(&u.x);
    __half2 b = *reinterpret_cast<__half2*>(&u.y);
    float2 x = __half22float2(a), y = __half22float2(b);
    return make_float4(x.x, x.y, y.x, y.y);
}

// ---------------- kernel 1: init ----------------
__global__ void k_init(const float* __restrict__ x) {
    int i = blockIdx.x * blockDim.x + threadIdx.x;
    if (i < N_NODES * NODE_DIMV) g_h1[i] = x[i];
    if (i < N_GRAPHS * HID) g_gsum[i] = 0.0f;
    if (i < N_GRAPHS) g_cnt[i] = 0.0f;
    if (i < N_NODES) { g_hist[i] = 0; g_fill[i] = 0; }
}

// ---------------- kernel 2: conv1 edges + dst histogram ----------------
__global__ void __launch_bounds__(256) k_conv1(
    const float* __restrict__ x, const float* __restrict__ ea,
    const int* __restrict__ src, const int* __restrict__ dst,
    const float* __restrict__ W1f, const float* __restrict__ b1f,
    const float* __restrict__ W1s, const float* __restrict__ b1s)
{
    __shared__ float swf[38 * 3], sws[38 * 3], sbf[3], sbs[3];
    int t = threadIdx.x;
    if (t < 114) { swf[t] = W1f[t]; sws[t] = W1s[t]; }
    if (t < 3)   { sbf[t] = b1f[t]; sbs[t] = b1s[t]; }
    __syncthreads();

    int e = blockIdx.x * blockDim.x + t;
    if (e >= N_EDGES) return;
    int s = src[e], d = dst[e];
    atomicAdd(&g_hist[d], 1);

    float xd[3], xs[3];
#pragma unroll
    for (int i = 0; i < 3; i++) { xd[i] = x[d * 3 + i]; xs[i] = x[s * 3 + i]; }

    float el[32];
    const float4* er = reinterpret_cast<const float4*>(ea + (size_t)e * 32);
#pragma unroll
    for (int q = 0; q < 8; q++) reinterpret_cast<float4*>(el)[q] = er[q];

#pragma unroll
    for (int c = 0; c < 3; c++) {
        float vf = sbf[c], vs = sbs[c];
#pragma unroll
        for (int i = 0; i < 3; i++) {
            vf += xd[i] * swf[i * 3 + c];        vs += xd[i] * sws[i * 3 + c];
            vf += xs[i] * swf[(3 + i) * 3 + c];  vs += xs[i] * sws[(3 + i) * 3 + c];
        }
#pragma unroll
        for (int k = 0; k < 32; k++) {
            vf += el[k] * swf[(6 + k) * 3 + c];
            vs += el[k] * sws[(6 + k) * 3 + c];
        }
        float m = sigf(vf) * spf(vs);
        atomicAdd(&g_h1[d * 3 + c], m);
    }
}

// ---------------- kernel 3: single-block exclusive scan ----------------
__global__ void __launch_bounds__(1024) k_scan() {
    __shared__ int s[1024];
    const int CH = (N_NODES + 1023) / 1024;
    int t = threadIdx.x;
    int lo = t * CH;
    int hi = lo + CH; if (hi > N_NODES) hi = N_NODES;
    int sum = 0;
    for (int i = lo; i < hi; i++) sum += g_hist[i];
    s[t] = sum;
    __syncthreads();
    for (int o = 1; o < 1024; o <<= 1) {
        int xv = (t >= o) ? s[t - o] : 0;
        __syncthreads();
        s[t] += xv;
        __syncthreads();
    }
    int run = s[t] - sum;
    for (int i = lo; i < hi; i++) {
        int c = g_hist[i];
        g_off[i] = run;
        run += c;
    }
}

// ---------------- kernel 4: fused scatter + materialize ----------------
__global__ void __launch_bounds__(256) k_sortmat(
    const float* __restrict__ ea, const int* __restrict__ src, const int* __restrict__ dst)
{
    int t = threadIdx.x;
    int e = blockIdx.x * 64 + (t >> 2);
    int q = t & 3;
    int lane = t & 31;

    int d = dst[e];
    int pos = 0;
    if (q == 0) pos = g_off[d] + atomicAdd(&g_fill[d], 1);
    pos = __shfl_sync(0xffffffffu, pos, lane & ~3);
    if (q == 0) { g_dsts[pos] = d; g_srcs[pos] = src[e]; }

    const float4* sp = reinterpret_cast<const float4*>(ea + (size_t)e * 32) + q * 2;
    float4 v0 = sp[0], v1 = sp[1];
    union { uint4 u; __half2 h2[4]; } o;
    o.h2[0] = __floats2half2_rn(v0.x, v0.y);
    o.h2[1] = __floats2half2_rn(v0.z, v0.w);
    o.h2[2] = __floats2half2_rn(v1.x, v1.y);
    o.h2[3] = __floats2half2_rn(v1.z, v1.w);
    reinterpret_cast<uint4*>(g_eas + (size_t)pos * 32)[q] = o.u;
}

// ---------------- node pre-projection GEMM (tf32 mma) -> g_P (fp16) ----------------
__global__ void __launch_bounds__(256, 2) k_gemm_node(
    const float* __restrict__ Wf, const float* __restrict__ Ws, int amode,
    const float* __restrict__ Wp, const float* __restrict__ bp)
{
    __shared__ uint32_t As[128][32];
    __shared__ uint32_t Bs[128][32];

    int t = threadIdx.x;
    int m0 = blockIdx.x * 128;
    int bn = blockIdx.y;
    const float* W = (bn & 1) ? Ws : Wf;
    int krow0 = (bn >> 1) * 128;

    int lane = t & 31, warp = t >> 5;
    int gid = lane >> 2, tig = lane & 3;
    int wm = warp >> 1, wn = warp & 1;

    float c[2][8][4] = {};

    for (int kc = 0; kc < 4; kc++) {
#pragma unroll
        for (int i = 0; i < 16; i++) {
            int idx = t + i * 256;
            int m = idx >> 5, k = idx & 31;
            int row = m0 + m;
            int cc = kc * 32 + k;
            float v = 0.0f;
            if (row < N_NODES) {
                if (amode == 2) {
                    float a = g_h1[row * 3], b = g_h1[row * 3 + 1], d = g_h1[row * 3 + 2];
                    v = fmaxf(bp[cc] + a * Wp[cc] + b * Wp[128 + cc] + d * Wp[256 + cc], 0.0f);
                    if (bn == 0) g_acc2[(size_t)row * HID + cc] = v;
                } else {
                    v = fmaxf(g_acc2[(size_t)row * HID + cc], 0.0f);
                    if (bn == 0) g_acc3[(size_t)row * HID + cc] = v;
                }
            }
            As[m][k ^ ((m & 7) << 2)] = to_tf32(v);
        }
#pragma unroll
        for (int i = 0; i < 16; i++) {
            int idx = t + i * 256;
            int k = idx >> 7, n = idx & 127;
            float v = W[(size_t)(krow0 + kc * 32 + k) * HID + n];
            Bs[n][k ^ ((n & 7) << 2)] = to_tf32(v);
        }
        __syncthreads();

#pragma unroll
        for (int ks = 0; ks < 4; ks++) {
            int k0 = ks * 8;
            uint32_t a[2][4];
#pragma unroll
            for (int mt = 0; mt < 2; mt++) {
                int m = wm * 32 + mt * 16 + gid;
                int sw = (m & 7) << 2;
                a[mt][0] = As[m][(k0 + tig) ^ sw];
                a[mt][1] = As[m + 8][(k0 + tig) ^ sw];
                a[mt][2] = As[m][(k0 + tig + 4) ^ sw];
                a[mt][3] = As[m + 8][(k0 + tig + 4) ^ sw];
            }
#pragma unroll
            for (int nt = 0; nt < 8; nt++) {
                int n = wn * 64 + nt * 8 + gid;
                int sw = (n & 7) << 2;
                uint32_t b[2] = { Bs[n][(k0 + tig) ^ sw], Bs[n][(k0 + tig + 4) ^ sw] };
                mma_tf32(c[0][nt], a[0], b);
                mma_tf32(c[1][nt], a[1], b);
            }
        }
        __syncthreads();
    }

    int rb = m0 + wm * 32;
#pragma unroll
    for (int mt = 0; mt < 2; mt++) {
#pragma unroll
        for (int nt = 0; nt < 8; nt++) {
            int r0 = rb + mt * 16 + gid;
            int cc = bn * 128 + wn * 64 + nt * 8 + 2 * tig;
            if (r0 < N_NODES)
                *reinterpret_cast<__half2*>(g_P + (size_t)r0 * 512 + cc) =
                    __floats2half2_rn(c[mt][nt][0], c[mt][nt][1]);
            int r1 = r0 + 8;
            if (r1 < N_NODES)
                *reinterpret_cast<__half2*>(g_P + (size_t)r1 * 512 + cc) =
                    __floats2half2_rn(c[mt][nt][2], c[mt][nt][3]);
        }
    }
}

// ---------------- fused conv edge kernel: multi-tile, weights staged ONCE per block ----
// Block processes TILES_PER_BLOCK consecutive 64-edge tiles. Weight slab [256x32]h
// staged once; per tile: stage As (seq), 2x fp16 HMMA halves, m-tiles to smem,
// two-pass edge phase (dst-run register accumulation + red4). 2 syncs per tile.
__global__ void __launch_bounds__(256, 3) k_fused5(
    const float* __restrict__ Wef, const float* __restrict__ Wes,
    const float* __restrict__ bf, const float* __restrict__ bs, int mode)
{
    extern __shared__ __align__(16) char sbuf[];
    __half (*Bs)[40]   = reinterpret_cast<__half(*)[40]>(sbuf + OFF_BS);
    __half (*As)[40]   = reinterpret_cast<__half(*)[40]>(sbuf + OFF_AS);
    __half (*smf)[132] = reinterpret_cast<__half(*)[132]>(sbuf + OFF_SMF);
    __half (*sms)[132] = reinterpret_cast<__half(*)[132]>(sbuf + OFF_SMS);

    __shared__ float sbf[128], sbs[128];
    __shared__ int sdst[64], ssrc[64];

    float* acc = (mode == 0) ? g_acc2 : g_acc3;
    int t = threadIdx.x;

    if (t < 128) sbf[t] = bf[t];
    else         sbs[t - 128] = bs[t - 128];

    // stage B once: both weight halves [256 x 32] fp16 (rows 0-127 = f, 128-255 = s)
    {
        int n = t, nn = t & 127;
        const float* W = (n < 128) ? Wef : Wes;
#pragma unroll
        for (int i = 0; i < 16; i++) {
            int k2 = i * 2;
            *reinterpret_cast<__half2*>(&Bs[n][k2]) =
                __floats2half2_rn(W[k2 * 128 + nn], W[(k2 + 1) * 128 + nn]);
        }
    }

    int lane = t & 31, warp = t >> 5;
    int gid = lane >> 2, tig = lane & 3;
    int wm = warp >> 2, wn = warp & 3;   // wm: 2x32 rows, wn: 4x32 cols
    int c0 = lane * 4;
    int base = warp * 8;

    for (int tile = 0; tile < TILES_PER_BLOCK; tile++) {
        int e0 = (blockIdx.x * TILES_PER_BLOCK + tile) * 64;

        // stage As: sorted fp16 edge attrs [64 x 32] (sequential stream)
        {
            int r = t >> 2, q = t & 3;
            const uint4* sp = reinterpret_cast<const uint4*>(g_eas + (size_t)(e0 + r) * 32);
            *reinterpret_cast<uint4*>(&As[r][q * 8]) = sp[q];
        }
        __syncthreads();   // sync1: As ready; all warps finished previous edge phase

        if (t < 64) { sdst[t] = g_dsts[e0 + t]; ssrc[t] = g_srcs[e0 + t]; }

        float c[2][4][4];

        // ---- GEMM f-half (Bs rows 0..127) ----
#pragma unroll
        for (int mt = 0; mt < 2; mt++)
#pragma unroll
            for (int nt = 0; nt < 4; nt++)
#pragma unroll
                for (int p = 0; p < 4; p++) c[mt][nt][p] = 0.0f;

#pragma unroll
        for (int ks = 0; ks < 2; ks++) {
            int k0 = ks * 16;
            uint32_t a[2][4];
#pragma unroll
            for (int mt = 0; mt < 2; mt++) {
                int m = wm * 32 + mt * 16 + gid;
                a[mt][0] = *reinterpret_cast<const uint32_t*>(&As[m][k0 + tig * 2]);
                a[mt][1] = *reinterpret_cast<const uint32_t*>(&As[m + 8][k0 + tig * 2]);
                a[mt][2] = *reinterpret_cast<const uint32_t*>(&As[m][k0 + 8 + tig * 2]);
                a[mt][3] = *reinterpret_cast<const uint32_t*>(&As[m + 8][k0 + 8 + tig * 2]);
            }
#pragma unroll
            for (int nt = 0; nt < 4; nt++) {
                int n = wn * 32 + nt * 8 + gid;
                uint32_t b[2] = {
                    *reinterpret_cast<const uint32_t*>(&Bs[n][k0 + tig * 2]),
                    *reinterpret_cast<const uint32_t*>(&Bs[n][k0 + 8 + tig * 2]) };
                mma_f16(c[0][nt], a[0], b);
                mma_f16(c[1][nt], a[1], b);
            }
        }
#pragma unroll
        for (int mt = 0; mt < 2; mt++) {
#pragma unroll
            for (int nt = 0; nt < 4; nt++) {
                int r = wm * 32 + mt * 16 + gid;
                int cc = wn * 32 + nt * 8 + 2 * tig;
                *reinterpret_cast<__half2*>(&smf[r][cc]) =
                    __floats2half2_rn(c[mt][nt][0], c[mt][nt][1]);
                *reinterpret_cast<__half2*>(&smf[r + 8][cc]) =
                    __floats2half2_rn(c[mt][nt][2], c[mt][nt][3]);
            }
        }

        // ---- GEMM s-half (Bs rows 128..255), reuse accumulators ----
#pragma unroll
        for (int mt = 0; mt < 2; mt++)
#pragma unroll
            for (int nt = 0; nt < 4; nt++)
#pragma unroll
                for (int p = 0; p < 4; p++) c[mt][nt][p] = 0.0f;

#pragma unroll
        for (int ks = 0; ks < 2; ks++) {
            int k0 = ks * 16;
            uint32_t a[2][4];
#pragma unroll
            for (int mt = 0; mt < 2; mt++) {
                int m = wm * 32 + mt * 16 + gid;
                a[mt][0] = *reinterpret_cast<const uint32_t*>(&As[m][k0 + tig * 2]);
                a[mt][1] = *reinterpret_cast<const uint32_t*>(&As[m + 8][k0 + tig * 2]);
                a[mt][2] = *reinterpret_cast<const uint32_t*>(&As[m][k0 + 8 + tig * 2]);
                a[mt][3] = *reinterpret_cast<const uint32_t*>(&As[m + 8][k0 + 8 + tig * 2]);
            }
#pragma unroll
            for (int nt = 0; nt < 4; nt++) {
                int n = 128 + wn * 32 + nt * 8 + gid;
                uint32_t b[2] = {
                    *reinterpret_cast<const uint32_t*>(&Bs[n][k0 + tig * 2]),
                    *reinterpret_cast<const uint32_t*>(&Bs[n][k0 + 8 + tig * 2]) };
                mma_f16(c[0][nt], a[0], b);
                mma_f16(c[1][nt], a[1], b);
            }
        }
#pragma unroll
        for (int mt = 0; mt < 2; mt++) {
#pragma unroll
            for (int nt = 0; nt < 4; nt++) {
                int r = wm * 32 + mt * 16 + gid;
                int cc = wn * 32 + nt * 8 + 2 * tig;
                *reinterpret_cast<__half2*>(&sms[r][cc]) =
                    __floats2half2_rn(c[mt][nt][0], c[mt][nt][1]);
                *reinterpret_cast<__half2*>(&sms[r + 8][cc]) =
                    __floats2half2_rn(c[mt][nt][2], c[mt][nt][3]);
            }
        }
        __syncthreads();   // sync2: m-tiles + sdst/ssrc ready

        // ---- edge phase: 8 edges per warp ----
        const float4 bfv = *reinterpret_cast<const float4*>(&sbf[c0]);
        const float4 bsv = *reinterpret_cast<const float4*>(&sbs[c0]);

        // pass 1: branch-free m computation, all gathers issued up front
        float4 mv[8];
#pragma unroll
        for (int j = 0; j < 8; j++) {
            int el = base + j;
            int d = sdst[el], s = ssrc[el];
            const __half* pd = g_P + (size_t)d * 512;
            const __half* ps = g_P + (size_t)s * 512;

            float4 ef = ldh4(&smf[el][c0]);
            float4 es = ldh4(&sms[el][c0]);
            float4 fd = ldh4(pd + c0);          // dst f-part (L1 hit within run)
            float4 sd = ldh4(pd + 128 + c0);    // dst s-part
            float4 fs = ldh4(ps + 256 + c0);    // src f-part
            float4 ss = ldh4(ps + 384 + c0);    // src s-part

            float vf0 = ef.x + fd.x + fs.x + bfv.x;
            float vf1 = ef.y + fd.y + fs.y + bfv.y;
            float vf2 = ef.z + fd.z + fs.z + bfv.z;
            float vf3 = ef.w + fd.w + fs.w + bfv.w;
            float vs0 = es.x + sd.x + ss.x + bsv.x;
            float vs1 = es.y + sd.y + ss.y + bsv.y;
            float vs2 = es.z + sd.z + ss.z + bsv.z;
            float vs3 = es.w + sd.w + ss.w + bsv.w;

            mv[j].x = sigf(vf0) * spf(vs0);
            mv[j].y = sigf(vf1) * spf(vs1);
            mv[j].z = sigf(vf2) * spf(vs2);
            mv[j].w = sigf(vf3) * spf(vs3);
        }

        // pass 2: register run accumulation, one red4 per dst run (warp-uniform)
        float a0 = 0.f, a1 = 0.f, a2 = 0.f, a3 = 0.f;
#pragma unroll
        for (int j = 0; j < 8; j++) {
            a0 += mv[j].x; a1 += mv[j].y; a2 += mv[j].z; a3 += mv[j].w;
            int d = sdst[base + j];
            bool flush = (j == 7) || (sdst[base + j + 1] != d);
            if (flush) {
                red4(acc + (size_t)d * 128 + c0, a0, a1, a2, a3);
                a0 = a1 = a2 = a3 = 0.f;
            }
        }
    }
}

// ---------------- pooling ----------------
__global__ void k_pool(const int* __restrict__ batch) {
    int i = blockIdx.x * blockDim.x + threadIdx.x;
    if (i >= N_NODES * 32) return;
    int n = i >> 5, q = i & 31;
    int b = batch[n];
    float4 v = *reinterpret_cast<const float4*>(&g_acc3[(size_t)n * 128 + q * 4]);
    v.x = fmaxf(v.x, 0.f); v.y = fmaxf(v.y, 0.f);
    v.z = fmaxf(v.z, 0.f); v.w = fmaxf(v.w, 0.f);
    red4(&g_gsum[(size_t)b * 128 + q * 4], v.x, v.y, v.z, v.w);
    if (q == 0) atomicAdd(&g_cnt[b], 1.0f);
}

// ---------------- head MLP ----------------
__global__ void __launch_bounds__(128) k_head(
    const float* __restrict__ Wfc, const float* __restrict__ bfc,
    const float* __restrict__ Wh, const float* __restrict__ bh,
    float* __restrict__ out)
{
    __shared__ float sg[128], sh[128];
    int b = blockIdx.x, t = threadIdx.x;
    float cnt = fmaxf(g_cnt[b], 1.0f);
    sg[t] = g_gsum[(size_t)b * 128 + t] / cnt;
    __syncthreads();
    float a = bfc[t];
#pragma unroll 8
    for (int k = 0; k < 128; k++) a += sg[k] * Wfc[k * 128 + t];
    sh[t] = fmaxf(a, 0.0f);
    __syncthreads();
    if (t < N_HEADSV) {
        float a2 = bh[t];
#pragma unroll 8
        for (int k = 0; k < 128; k++) a2 += sh[k] * Wh[k * 5 + t];
        out[b * 5 + t] = a2;
    }
}

// ---------------- launch ----------------
extern "C" void kernel_launch(void* const* d_in, const int* in_sizes, int n_in,
                              void* d_out, int out_size) {
    (void)in_sizes; (void)n_in; (void)out_size;
    const float* x    = (const float*)d_in[0];
    const float* ea   = (const float*)d_in[1];
    const int*   ei   = (const int*)d_in[2];
    const int*   batch= (const int*)d_in[3];
    const float* W1f  = (const float*)d_in[4];
    const float* b1f  = (const float*)d_in[5];
    const float* W1s  = (const float*)d_in[6];
    const float* b1s  = (const float*)d_in[7];
    const float* Wp   = (const float*)d_in[8];
    const float* bp   = (const float*)d_in[9];
    const float* W2f  = (const float*)d_in[10];
    const float* b2f  = (const float*)d_in[11];
    const float* W2s  = (const float*)d_in[12];
    const float* b2s  = (const float*)d_in[13];
    const float* W3f  = (const float*)d_in[14];
    const float* b3f  = (const float*)d_in[15];
    const float* W3s  = (const float*)d_in[16];
    const float* b3s  = (const float*)d_in[17];
    const float* Wfc  = (const float*)d_in[18];
    const float* bfc  = (const float*)d_in[19];
    const float* Wh   = (const float*)d_in[20];
    const float* bh   = (const float*)d_in[21];
    const int* src = ei;
    const int* dst = ei + N_EDGES;
    float* out = (float*)d_out;

    static int smem_set = 0;
    if (!smem_set) {
        cudaFuncSetAttribute(k_fused5, cudaFuncAttributeMaxDynamicSharedMemorySize,
                             SMEM_FUSED);
        smem_set = 1;
    }

    // 1) init
    k_init<<<(N_NODES * NODE_DIMV + 255) / 256, 256>>>(x);
    // 2) conv1 + dst histogram
    k_conv1<<<(N_EDGES + 255) / 256, 256>>>(x, ea, src, dst, W1f, b1f, W1s, b1s);
    // 3) scan
    k_scan<<<1, 1024>>>();
    // 4) fused scatter + materialize sorted fp16 edge data
    k_sortmat<<<N_EDGES / 64, 256>>>(ea, src, dst);

    // 5) conv2
    k_gemm_node<<<dim3(391, 4), 256>>>(W2f, W2s, 2, Wp, bp);
    k_fused5<<<NBLK, 256, SMEM_FUSED>>>(W2f + 256 * 128, W2s + 256 * 128, b2f, b2s, 0);

    // 6) conv3
    k_gemm_node<<<dim3(391, 4), 256>>>(W3f, W3s, 1, Wp, bp);
    k_fused5<<<NBLK, 256, SMEM_FUSED>>>(W3f + 256 * 128, W3s + 256 * 128, b3f, b3s, 1);

    // 7) pooling + head
    k_pool<<<(N_NODES * 32 + 255) / 256, 256>>>(batch);
    k_head<<<N_GRAPHS, 128>>>(Wfc, bfc, Wh, bh, out);
}

// round 15
// speedup vs baseline: 1.0116x; 1.0116x over previous
#include <cuda_runtime.h>
#include <cuda_fp16.h>
#include <cstdint>

#define N_NODES 50000
#define N_EDGES 1600000
#define NODE_DIMV 3
#define HID 128
#define N_GRAPHS 512
#define N_HEADSV 5

// ---------------- device scratch ----------------
__device__ float  g_h1[N_NODES * NODE_DIMV];      // conv1 output
__device__ float  g_acc2[N_NODES * HID];          // conv2 accumulator (init = h2)
__device__ float  g_acc3[N_NODES * HID];          // conv3 accumulator (init = relu(acc2))
__device__ __half g_P[N_NODES * 512];             // node proj table: [fd|sd|fs|ss] per node
__device__ float  g_gsum[N_GRAPHS * HID];
__device__ float  g_cnt[N_GRAPHS];
// dst-sort scratch + materialized sorted edge data (fp16)
__device__ int    g_hist[N_NODES];
__device__ int    g_off[N_NODES];
__device__ int    g_fill[N_NODES];
__device__ __half g_eas[(size_t)N_EDGES * 32];    // edge attrs, dst-sorted, fp16
__device__ int    g_srcs[N_EDGES];                // src in sorted order
__device__ int    g_dsts[N_EDGES];                // dst in sorted order

// ---------------- fast activations (2 MUFU per channel instead of 4) ----------------
// sigmoid via HW tanh: 1 MUFU (tanh.approx.f32), rel err ~2^-11
__device__ __forceinline__ float sigf(float v) {
    float t;
    asm("tanh.approx.f32 %0, %1;" : "=f"(t) : "f"(0.5f * v));
    return fmaf(0.5f, t, 0.5f);
}
// softplus: max(v,0) + ln(1+t), t=e^-|v| in (0,1]. ln(1+t) = deg-8 Taylor of
// ln(1.5+u) at u=t-0.5 (|u|<=0.5, trunc err <= 5.6e-6 abs). 1 MUFU (EX2) + 9 FMA.
__device__ __forceinline__ float spf(float v) {
    float a = fabsf(v);
    float t = __expf(-a);                 // 1 MUFU (EX2)
    float u = t - 0.5f;
    float p = -0.00487730530f;
    p = fmaf(p, u,  0.00836109480f);
    p = fmaf(p, u, -0.0146319159f);
    p = fmaf(p, u,  0.0263374486f);
    p = fmaf(p, u, -0.0493827160f);
    p = fmaf(p, u,  0.0987654321f);
    p = fmaf(p, u, -0.222222222f);
    p = fmaf(p, u,  0.666666667f);
    p = fmaf(p, u,  0.405465108f);        // ln(1+t)
    return fmaxf(v, 0.0f) + p;
}
__device__ __forceinline__ void red4(float* p, float a, float b, float c, float d) {
    asm volatile("red.global.add.v4.f32 [%0], {%1,%2,%3,%4};"
                 :: "l"(p), "f"(a), "f"(b), "f"(c), "f"(d) : "memory");
}
__device__ __forceinline__ uint32_t to_tf32(float v) {
    uint32_t r; asm("cvt.rna.tf32.f32 %0, %1;" : "=r"(r) : "f"(v)); return r;
}
__device__ __forceinline__ void mma_tf32(float c[4], const uint32_t a[4], const uint32_t b[2]) {
    asm volatile(
        "mma.sync.aligned.m16n8k8.row.col.f32.tf32.tf32.f32 "
        "{%0,%1,%2,%3},{%4,%5,%6,%7},{%8,%9},{%0,%1,%2,%3};"
        : "+f"(c[0]), "+f"(c[1]), "+f"(c[2]), "+f"(c[3])
        : "r"(a[0]), "r"(a[1]), "r"(a[2]), "r"(a[3]), "r"(b[0]), "r"(b[1]));
}
__device__ __forceinline__ void mma_f16(float c[4], const uint32_t a[4], const uint32_t b[2]) {
    asm volatile(
        "mma.sync.aligned.m16n8k16.row.col.f32.f16.f16.f32 "
        "{%0,%1,%2,%3},{%4,%5,%6,%7},{%8,%9},{%0,%1,%2,%3};"
        : "+f"(c[0]), "+f"(c[1]), "+f"(c[2]), "+f"(c[3])
        : "r"(a[0]), "r"(a[1]), "r"(a[2]), "r"(a[3]), "r"(b[0]), "r"(b[1]));
}
__device__ __forceinline__ float4 ldh4(const __half* p) {
    uint2 u = *reinterpret_cast<const uint2*>(p);
    __half2 a = *reinterpret_cast<__half2*>(&u.x);
    __half2 b = *reinterpret_cast<__half2*>(&u.y);
    float2 x = __half22float2(a), y = __half22float2(b);
    return make_float4(x.x, x.y, y.x, y.y);
}

// ---------------- kernel 1: init ----------------
__global__ void k_init(const float* __restrict__ x) {
    int i = blockIdx.x * blockDim.x + threadIdx.x;
    if (i < N_NODES * NODE_DIMV) g_h1[i] = x[i];
    if (i < N_GRAPHS * HID) g_gsum[i] = 0.0f;
    if (i < N_GRAPHS) g_cnt[i] = 0.0f;
    if (i < N_NODES) { g_hist[i] = 0; g_fill[i] = 0; }
}

// ---------------- kernel 2: conv1 edges + dst histogram ----------------
__global__ void __launch_bounds__(256) k_conv1(
    const float* __restrict__ x, const float* __restrict__ ea,
    const int* __restrict__ src, const int* __restrict__ dst,
    const float* __restrict__ W1f, const float* __restrict__ b1f,
    const float* __restrict__ W1s, const float* __restrict__ b1s)
{
    __shared__ float swf[38 * 3], sws[38 * 3], sbf[3], sbs[3];
    int t = threadIdx.x;
    if (t < 114) { swf[t] = W1f[t]; sws[t] = W1s[t]; }
    if (t < 3)   { sbf[t] = b1f[t]; sbs[t] = b1s[t]; }
    __syncthreads();

    int e = blockIdx.x * blockDim.x + t;
    if (e >= N_EDGES) return;
    int s = src[e], d = dst[e];
    atomicAdd(&g_hist[d], 1);

    float xd[3], xs[3];
#pragma unroll
    for (int i = 0; i < 3; i++) { xd[i] = x[d * 3 + i]; xs[i] = x[s * 3 + i]; }

    float el[32];
    const float4* er = reinterpret_cast<const float4*>(ea + (size_t)e * 32);
#pragma unroll
    for (int q = 0; q < 8; q++) reinterpret_cast<float4*>(el)[q] = er[q];

#pragma unroll
    for (int c = 0; c < 3; c++) {
        float vf = sbf[c], vs = sbs[c];
#pragma unroll
        for (int i = 0; i < 3; i++) {
            vf += xd[i] * swf[i * 3 + c];        vs += xd[i] * sws[i * 3 + c];
            vf += xs[i] * swf[(3 + i) * 3 + c];  vs += xs[i] * sws[(3 + i) * 3 + c];
        }
#pragma unroll
        for (int k = 0; k < 32; k++) {
            vf += el[k] * swf[(6 + k) * 3 + c];
            vs += el[k] * sws[(6 + k) * 3 + c];
        }
        float m = sigf(vf) * spf(vs);
        atomicAdd(&g_h1[d * 3 + c], m);
    }
}

// ---------------- kernel 3: single-block exclusive scan ----------------
__global__ void __launch_bounds__(1024) k_scan() {
    __shared__ int s[1024];
    const int CH = (N_NODES + 1023) / 1024;
    int t = threadIdx.x;
    int lo = t * CH;
    int hi = lo + CH; if (hi > N_NODES) hi = N_NODES;
    int sum = 0;
    for (int i = lo; i < hi; i++) sum += g_hist[i];
    s[t] = sum;
    __syncthreads();
    for (int o = 1; o < 1024; o <<= 1) {
        int xv = (t >= o) ? s[t - o] : 0;
        __syncthreads();
        s[t] += xv;
        __syncthreads();
    }
    int run = s[t] - sum;
    for (int i = lo; i < hi; i++) {
        int c = g_hist[i];
        g_off[i] = run;
        run += c;
    }
}

// ---------------- kernel 4: fused scatter + materialize ----------------
__global__ void __launch_bounds__(256) k_sortmat(
    const float* __restrict__ ea, const int* __restrict__ src, const int* __restrict__ dst)
{
    int t = threadIdx.x;
    int e = blockIdx.x * 64 + (t >> 2);
    int q = t & 3;
    int lane = t & 31;

    int d = dst[e];
    int pos = 0;
    if (q == 0) pos = g_off[d] + atomicAdd(&g_fill[d], 1);
    pos = __shfl_sync(0xffffffffu, pos, lane & ~3);
    if (q == 0) { g_dsts[pos] = d; g_srcs[pos] = src[e]; }

    const float4* sp = reinterpret_cast<const float4*>(ea + (size_t)e * 32) + q * 2;
    float4 v0 = sp[0], v1 = sp[1];
    union { uint4 u; __half2 h2[4]; } o;
    o.h2[0] = __floats2half2_rn(v0.x, v0.y);
    o.h2[1] = __floats2half2_rn(v0.z, v0.w);
    o.h2[2] = __floats2half2_rn(v1.x, v1.y);
    o.h2[3] = __floats2half2_rn(v1.z, v1.w);
    reinterpret_cast<uint4*>(g_eas + (size_t)pos * 32)[q] = o.u;
}

// ---------------- node pre-projection GEMM (tf32 mma) -> g_P (fp16) ----------------
__global__ void __launch_bounds__(256, 2) k_gemm_node(
    const float* __restrict__ Wf, const float* __restrict__ Ws, int amode,
    const float* __restrict__ Wp, const float* __restrict__ bp)
{
    __shared__ uint32_t As[128][32];
    __shared__ uint32_t Bs[128][32];

    int t = threadIdx.x;
    int m0 = blockIdx.x * 128;
    int bn = blockIdx.y;
    const float* W = (bn & 1) ? Ws : Wf;
    int krow0 = (bn >> 1) * 128;

    int lane = t & 31, warp = t >> 5;
    int gid = lane >> 2, tig = lane & 3;
    int wm = warp >> 1, wn = warp & 1;

    float c[2][8][4] = {};

    for (int kc = 0; kc < 4; kc++) {
#pragma unroll
        for (int i = 0; i < 16; i++) {
            int idx = t + i * 256;
            int m = idx >> 5, k = idx & 31;
            int row = m0 + m;
            int cc = kc * 32 + k;
            float v = 0.0f;
            if (row < N_NODES) {
                if (amode == 2) {
                    float a = g_h1[row * 3], b = g_h1[row * 3 + 1], d = g_h1[row * 3 + 2];
                    v = fmaxf(bp[cc] + a * Wp[cc] + b * Wp[128 + cc] + d * Wp[256 + cc], 0.0f);
                    if (bn == 0) g_acc2[(size_t)row * HID + cc] = v;
                } else {
                    v = fmaxf(g_acc2[(size_t)row * HID + cc], 0.0f);
                    if (bn == 0) g_acc3[(size_t)row * HID + cc] = v;
                }
            }
            As[m][k ^ ((m & 7) << 2)] = to_tf32(v);
        }
#pragma unroll
        for (int i = 0; i < 16; i++) {
            int idx = t + i * 256;
            int k = idx >> 7, n = idx & 127;
            float v = W[(size_t)(krow0 + kc * 32 + k) * HID + n];
            Bs[n][k ^ ((n & 7) << 2)] = to_tf32(v);
        }
        __syncthreads();

#pragma unroll
        for (int ks = 0; ks < 4; ks++) {
            int k0 = ks * 8;
            uint32_t a[2][4];
#pragma unroll
            for (int mt = 0; mt < 2; mt++) {
                int m = wm * 32 + mt * 16 + gid;
                int sw = (m & 7) << 2;
                a[mt][0] = As[m][(k0 + tig) ^ sw];
                a[mt][1] = As[m + 8][(k0 + tig) ^ sw];
                a[mt][2] = As[m][(k0 + tig + 4) ^ sw];
                a[mt][3] = As[m + 8][(k0 + tig + 4) ^ sw];
            }
#pragma unroll
            for (int nt = 0; nt < 8; nt++) {
                int n = wn * 64 + nt * 8 + gid;
                int sw = (n & 7) << 2;
                uint32_t b[2] = { Bs[n][(k0 + tig) ^ sw], Bs[n][(k0 + tig + 4) ^ sw] };
                mma_tf32(c[0][nt], a[0], b);
                mma_tf32(c[1][nt], a[1], b);
            }
        }
        __syncthreads();
    }

    int rb = m0 + wm * 32;
#pragma unroll
    for (int mt = 0; mt < 2; mt++) {
#pragma unroll
        for (int nt = 0; nt < 8; nt++) {
            int r0 = rb + mt * 16 + gid;
            int cc = bn * 128 + wn * 64 + nt * 8 + 2 * tig;
            if (r0 < N_NODES)
                *reinterpret_cast<__half2*>(g_P + (size_t)r0 * 512 + cc) =
                    __floats2half2_rn(c[mt][nt][0], c[mt][nt][1]);
            int r1 = r0 + 8;
            if (r1 < N_NODES)
                *reinterpret_cast<__half2*>(g_P + (size_t)r1 * 512 + cc) =
                    __floats2half2_rn(c[mt][nt][2], c[mt][nt][3]);
        }
    }
}

// ---------------- fused conv edge kernel (fp16 HMMA, sorted, streamed) ----------------
// One block = 64 sorted edges. Single staging of ea[64x32]h + BOTH weight halves
// [256x32]h. Two fp16 m16n8k16 GEMM passes share one accumulator array; 3 syncs.
// Then two-pass edge phase with dst-run register accumulation.
__global__ void __launch_bounds__(256, 3) k_fused4(
    const float* __restrict__ Wef, const float* __restrict__ Wes,
    const float* __restrict__ bf, const float* __restrict__ bs, int mode)
{
    __shared__ __align__(16) char sbuf[25600];
    __shared__ __align__(16) __half smf[64][132];
    __shared__ float sbf[128], sbs[128];
    __shared__ int sdst[64], ssrc[64];

    __half (*As)[40]  = reinterpret_cast<__half(*)[40]>(sbuf);
    __half (*Bs)[40]  = reinterpret_cast<__half(*)[40]>(sbuf + 5120);
    __half (*sms)[132] = reinterpret_cast<__half(*)[132]>(sbuf);

    float* acc = (mode == 0) ? g_acc2 : g_acc3;
    int t = threadIdx.x;
    int e0 = blockIdx.x * 64;

    if (t < 128) sbf[t] = bf[t];
    else         sbs[t - 128] = bs[t - 128];
    if (t < 64) { sdst[t] = g_dsts[e0 + t]; ssrc[t] = g_srcs[e0 + t]; }

    // stage A: sorted fp16 edge attrs [64 x 32]
    {
        int r = t >> 2, q = t & 3;
        const uint4* sp = reinterpret_cast<const uint4*>(g_eas + (size_t)(e0 + r) * 32);
        *reinterpret_cast<uint4*>(&As[r][q * 8]) = sp[q];
    }
    // stage B: both weight halves [256 x 32] fp16 (rows 0-127 = f, 128-255 = s)
    {
        int n = t, nn = t & 127;
        const float* W = (n < 128) ? Wef : Wes;
#pragma unroll
        for (int i = 0; i < 16; i++) {
            int k2 = i * 2;
            *reinterpret_cast<__half2*>(&Bs[n][k2]) =
                __floats2half2_rn(W[k2 * 128 + nn], W[(k2 + 1) * 128 + nn]);
        }
    }
    __syncthreads();

    int lane = t & 31, warp = t >> 5;
    int gid = lane >> 2, tig = lane & 3;
    int wm = warp >> 2, wn = warp & 3;   // wm: 2x32 rows, wn: 4x32 cols

    float c[2][4][4];

    // ---- GEMM f-half (Bs rows 0..127) ----
#pragma unroll
    for (int mt = 0; mt < 2; mt++)
#pragma unroll
        for (int nt = 0; nt < 4; nt++)
#pragma unroll
            for (int p = 0; p < 4; p++) c[mt][nt][p] = 0.0f;

#pragma unroll
    for (int ks = 0; ks < 2; ks++) {
        int k0 = ks * 16;
        uint32_t a[2][4];
#pragma unroll
        for (int mt = 0; mt < 2; mt++) {
            int m = wm * 32 + mt * 16 + gid;
            a[mt][0] = *reinterpret_cast<const uint32_t*>(&As[m][k0 + tig * 2]);
            a[mt][1] = *reinterpret_cast<const uint32_t*>(&As[m + 8][k0 + tig * 2]);
            a[mt][2] = *reinterpret_cast<const uint32_t*>(&As[m][k0 + 8 + tig * 2]);
            a[mt][3] = *reinterpret_cast<const uint32_t*>(&As[m + 8][k0 + 8 + tig * 2]);
        }
#pragma unroll
        for (int nt = 0; nt < 4; nt++) {
            int n = wn * 32 + nt * 8 + gid;
            uint32_t b[2] = {
                *reinterpret_cast<const uint32_t*>(&Bs[n][k0 + tig * 2]),
                *reinterpret_cast<const uint32_t*>(&Bs[n][k0 + 8 + tig * 2]) };
            mma_f16(c[0][nt], a[0], b);
            mma_f16(c[1][nt], a[1], b);
        }
    }
#pragma unroll
    for (int mt = 0; mt < 2; mt++) {
#pragma unroll
        for (int nt = 0; nt < 4; nt++) {
            int r = wm * 32 + mt * 16 + gid;
            int cc = wn * 32 + nt * 8 + 2 * tig;
            *reinterpret_cast<__half2*>(&smf[r][cc]) =
                __floats2half2_rn(c[mt][nt][0], c[mt][nt][1]);
            *reinterpret_cast<__half2*>(&smf[r + 8][cc]) =
                __floats2half2_rn(c[mt][nt][2], c[mt][nt][3]);
        }
    }

    // ---- GEMM s-half (Bs rows 128..255), reuse accumulators ----
#pragma unroll
    for (int mt = 0; mt < 2; mt++)
#pragma unroll
        for (int nt = 0; nt < 4; nt++)
#pragma unroll
            for (int p = 0; p < 4; p++) c[mt][nt][p] = 0.0f;

#pragma unroll
    for (int ks = 0; ks < 2; ks++) {
        int k0 = ks * 16;
        uint32_t a[2][4];
#pragma unroll
        for (int mt = 0; mt < 2; mt++) {
            int m = wm * 32 + mt * 16 + gid;
            a[mt][0] = *reinterpret_cast<const uint32_t*>(&As[m][k0 + tig * 2]);
            a[mt][1] = *reinterpret_cast<const uint32_t*>(&As[m + 8][k0 + tig * 2]);
            a[mt][2] = *reinterpret_cast<const uint32_t*>(&As[m][k0 + 8 + tig * 2]);
            a[mt][3] = *reinterpret_cast<const uint32_t*>(&As[m + 8][k0 + 8 + tig * 2]);
        }
#pragma unroll
        for (int nt = 0; nt < 4; nt++) {
            int n = 128 + wn * 32 + nt * 8 + gid;
            uint32_t b[2] = {
                *reinterpret_cast<const uint32_t*>(&Bs[n][k0 + tig * 2]),
                *reinterpret_cast<const uint32_t*>(&Bs[n][k0 + 8 + tig * 2]) };
            mma_f16(c[0][nt], a[0], b);
            mma_f16(c[1][nt], a[1], b);
        }
    }
    __syncthreads();   // all warps done reading As/Bs — safe to alias with sms

    // write s m-tile into aliased region
#pragma unroll
    for (int mt = 0; mt < 2; mt++) {
#pragma unroll
        for (int nt = 0; nt < 4; nt++) {
            int r = wm * 32 + mt * 16 + gid;
            int cc = wn * 32 + nt * 8 + 2 * tig;
            *reinterpret_cast<__half2*>(&sms[r][cc]) =
                __floats2half2_rn(c[mt][nt][0], c[mt][nt][1]);
            *reinterpret_cast<__half2*>(&sms[r + 8][cc]) =
                __floats2half2_rn(c[mt][nt][2], c[mt][nt][3]);
        }
    }
    __syncthreads();

    // ---- edge phase: 8 edges per warp ----
    int c0 = lane * 4;
    const float4 bfv = *reinterpret_cast<const float4*>(&sbf[c0]);
    const float4 bsv = *reinterpret_cast<const float4*>(&sbs[c0]);
    int base = warp * 8;

    // pass 1: branch-free m computation, all gathers issued up front
    float4 mv[8];
#pragma unroll
    for (int j = 0; j < 8; j++) {
        int el = base + j;
        int d = sdst[el], s = ssrc[el];
        const __half* pd = g_P + (size_t)d * 512;
        const __half* ps = g_P + (size_t)s * 512;

        float4 ef = ldh4(&smf[el][c0]);
        float4 es = ldh4(&sms[el][c0]);
        float4 fd = ldh4(pd + c0);          // dst f-part (L1 hit within run)
        float4 sd = ldh4(pd + 128 + c0);    // dst s-part
        float4 fs = ldh4(ps + 256 + c0);    // src f-part
        float4 ss = ldh4(ps + 384 + c0);    // src s-part

        float vf0 = ef.x + fd.x + fs.x + bfv.x;
        float vf1 = ef.y + fd.y + fs.y + bfv.y;
        float vf2 = ef.z + fd.z + fs.z + bfv.z;
        float vf3 = ef.w + fd.w + fs.w + bfv.w;
        float vs0 = es.x + sd.x + ss.x + bsv.x;
        float vs1 = es.y + sd.y + ss.y + bsv.y;
        float vs2 = es.z + sd.z + ss.z + bsv.z;
        float vs3 = es.w + sd.w + ss.w + bsv.w;

        mv[j].x = sigf(vf0) * spf(vs0);
        mv[j].y = sigf(vf1) * spf(vs1);
        mv[j].z = sigf(vf2) * spf(vs2);
        mv[j].w = sigf(vf3) * spf(vs3);
    }

    // pass 2: register run accumulation, one red4 per dst run (warp-uniform)
    float a0 = 0.f, a1 = 0.f, a2 = 0.f, a3 = 0.f;
#pragma unroll
    for (int j = 0; j < 8; j++) {
        a0 += mv[j].x; a1 += mv[j].y; a2 += mv[j].z; a3 += mv[j].w;
        int d = sdst[base + j];
        bool flush = (j == 7) || (sdst[base + j + 1] != d);
        if (flush) {
            red4(acc + (size_t)d * 128 + c0, a0, a1, a2, a3);
            a0 = a1 = a2 = a3 = 0.f;
        }
    }
}

// ---------------- pooling ----------------
__global__ void k_pool(const int* __restrict__ batch) {
    int i = blockIdx.x * blockDim.x + threadIdx.x;
    if (i >= N_NODES * 32) return;
    int n = i >> 5, q = i & 31;
    int b = batch[n];
    float4 v = *reinterpret_cast<const float4*>(&g_acc3[(size_t)n * 128 + q * 4]);
    v.x = fmaxf(v.x, 0.f); v.y = fmaxf(v.y, 0.f);
    v.z = fmaxf(v.z, 0.f); v.w = fmaxf(v.w, 0.f);
    red4(&g_gsum[(size_t)b * 128 + q * 4], v.x, v.y, v.z, v.w);
    if (q == 0) atomicAdd(&g_cnt[b], 1.0f);
}

// ---------------- head MLP ----------------
__global__ void __launch_bounds__(128) k_head(
    const float* __restrict__ Wfc, const float* __restrict__ bfc,
    const float* __restrict__ Wh, const float* __restrict__ bh,
    float* __restrict__ out)
{
    __shared__ float sg[128], sh[128];
    int b = blockIdx.x, t = threadIdx.x;
    float cnt = fmaxf(g_cnt[b], 1.0f);
    sg[t] = g_gsum[(size_t)b * 128 + t] / cnt;
    __syncthreads();
    float a = bfc[t];
#pragma unroll 8
    for (int k = 0; k < 128; k++) a += sg[k] * Wfc[k * 128 + t];
    sh[t] = fmaxf(a, 0.0f);
    __syncthreads();
    if (t < N_HEADSV) {
        float a2 = bh[t];
#pragma unroll 8
        for (int k = 0; k < 128; k++) a2 += sh[k] * Wh[k * 5 + t];
        out[b * 5 + t] = a2;
    }
}

// ---------------- launch ----------------
extern "C" void kernel_launch(void* const* d_in, const int* in_sizes, int n_in,
                              void* d_out, int out_size) {
    (void)in_sizes; (void)n_in; (void)out_size;
    const float* x    = (const float*)d_in[0];
    const float* ea   = (const float*)d_in[1];
    const int*   ei   = (const int*)d_in[2];
    const int*   batch= (const int*)d_in[3];
    const float* W1f  = (const float*)d_in[4];
    const float* b1f  = (const float*)d_in[5];
    const float* W1s  = (const float*)d_in[6];
    const float* b1s  = (const float*)d_in[7];
    const float* Wp   = (const float*)d_in[8];
    const float* bp   = (const float*)d_in[9];
    const float* W2f  = (const float*)d_in[10];
    const float* b2f  = (const float*)d_in[11];
    const float* W2s  = (const float*)d_in[12];
    const float* b2s  = (const float*)d_in[13];
    const float* W3f  = (const float*)d_in[14];
    const float* b3f  = (const float*)d_in[15];
    const float* W3s  = (const float*)d_in[16];
    const float* b3s  = (const float*)d_in[17];
    const float* Wfc  = (const float*)d_in[18];
    const float* bfc  = (const float*)d_in[19];
    const float* Wh   = (const float*)d_in[20];
    const float* bh   = (const float*)d_in[21];
    const int* src = ei;
    const int* dst = ei + N_EDGES;
    float* out = (float*)d_out;

    // 1) init
    k_init<<<(N_NODES * NODE_DIMV + 255) / 256, 256>>>(x);
    // 2) conv1 + dst histogram
    k_conv1<<<(N_EDGES + 255) / 256, 256>>>(x, ea, src, dst, W1f, b1f, W1s, b1s);
    // 3) scan
    k_scan<<<1, 1024>>>();
    // 4) fused scatter + materialize sorted fp16 edge data
    k_sortmat<<<N_EDGES / 64, 256>>>(ea, src, dst);

    // 5) conv2
    k_gemm_node<<<dim3(391, 4), 256>>>(W2f, W2s, 2, Wp, bp);
    k_fused4<<<N_EDGES / 64, 256>>>(W2f + 256 * 128, W2s + 256 * 128, b2f, b2s, 0);  // launch #6: profiled

    // 6) conv3
    k_gemm_node<<<dim3(391, 4), 256>>>(W3f, W3s, 1, Wp, bp);
    k_fused4<<<N_EDGES / 64, 256>>>(W3f + 256 * 128, W3s + 256 * 128, b3f, b3s, 1);

    // 7) pooling + head
    k_pool<<<(N_NODES * 32 + 255) / 256, 256>>>(batch);
    k_head<<<N_GRAPHS, 128>>>(Wfc, bfc, Wh, bh, out);
}

// round 16
// speedup vs baseline: 1.0592x; 1.0470x over previous
#include <cuda_runtime.h>
#include <cuda_fp16.h>
#include <cstdint>

#define N_NODES 50000
#define N_EDGES 1600000
#define NODE_DIMV 3
#define HID 128
#define N_GRAPHS 512
#define N_HEADSV 5

// ---------------- device scratch ----------------
__device__ float  g_h1[N_NODES * NODE_DIMV];      // conv1 output
__device__ float  g_acc2[N_NODES * HID];          // conv2 accumulator (init = h2)
__device__ float  g_acc3[N_NODES * HID];          // conv3 accumulator (init = relu(acc2))
// node proj table, quad-interleaved: per node 512 halves =
//   [0..255]   dst part: for lane L: [f(4L..4L+3) | s(4L..4L+3)] at offset 8L
//   [256..511] src part: same layout
__device__ __half g_P[N_NODES * 512];
__device__ float  g_gsum[N_GRAPHS * HID];
__device__ float  g_cnt[N_GRAPHS];
// dst-sort scratch + materialized sorted edge data (fp16)
__device__ int    g_hist[N_NODES];
__device__ int    g_off[N_NODES];
__device__ int    g_fill[N_NODES];
__device__ __half g_eas[(size_t)N_EDGES * 32];    // edge attrs, dst-sorted, fp16
__device__ int    g_srcs[N_EDGES];                // src in sorted order
__device__ int    g_dsts[N_EDGES];                // dst in sorted order

// ---------------- fast activations (2 MUFU per channel) ----------------
__device__ __forceinline__ float sigf(float v) {
    float t;
    asm("tanh.approx.f32 %0, %1;" : "=f"(t) : "f"(0.5f * v));
    return fmaf(0.5f, t, 0.5f);
}
// softplus: max(v,0) + ln(1+t), t=e^-|v|; ln via deg-8 poly (trunc err <= 5.6e-6)
__device__ __forceinline__ float spf(float v) {
    float a = fabsf(v);
    float t = __expf(-a);
    float u = t - 0.5f;
    float p = -0.00487730530f;
    p = fmaf(p, u,  0.00836109480f);
    p = fmaf(p, u, -0.0146319159f);
    p = fmaf(p, u,  0.0263374486f);
    p = fmaf(p, u, -0.0493827160f);
    p = fmaf(p, u,  0.0987654321f);
    p = fmaf(p, u, -0.222222222f);
    p = fmaf(p, u,  0.666666667f);
    p = fmaf(p, u,  0.405465108f);
    return fmaxf(v, 0.0f) + p;
}
__device__ __forceinline__ void red4(float* p, float a, float b, float c, float d) {
    asm volatile("red.global.add.v4.f32 [%0], {%1,%2,%3,%4};"
                 :: "l"(p), "f"(a), "f"(b), "f"(c), "f"(d) : "memory");
}
__device__ __forceinline__ uint32_t to_tf32(float v) {
    uint32_t r; asm("cvt.rna.tf32.f32 %0, %1;" : "=r"(r) : "f"(v)); return r;
}
__device__ __forceinline__ void mma_tf32(float c[4], const uint32_t a[4], const uint32_t b[2]) {
    asm volatile(
        "mma.sync.aligned.m16n8k8.row.col.f32.tf32.tf32.f32 "
        "{%0,%1,%2,%3},{%4,%5,%6,%7},{%8,%9},{%0,%1,%2,%3};"
        : "+f"(c[0]), "+f"(c[1]), "+f"(c[2]), "+f"(c[3])
        : "r"(a[0]), "r"(a[1]), "r"(a[2]), "r"(a[3]), "r"(b[0]), "r"(b[1]));
}
__device__ __forceinline__ void mma_f16(float c[4], const uint32_t a[4], const uint32_t b[2]) {
    asm volatile(
        "mma.sync.aligned.m16n8k16.row.col.f32.f16.f16.f32 "
        "{%0,%1,%2,%3},{%4,%5,%6,%7},{%8,%9},{%0,%1,%2,%3};"
        : "+f"(c[0]), "+f"(c[1]), "+f"(c[2]), "+f"(c[3])
        : "r"(a[0]), "r"(a[1]), "r"(a[2]), "r"(a[3]), "r"(b[0]), "r"(b[1]));
}
__device__ __forceinline__ float4 ldh4(const __half* p) {
    uint2 u = *reinterpret_cast<const uint2*>(p);
    __half2 a = *reinterpret_cast<__half2*>(&u.x);
    __half2 b = *reinterpret_cast<__half2*>(&u.y);
    float2 x = __half22float2(a), y = __half22float2(b);
    return make_float4(x.x, x.y, y.x, y.y);
}
// load 8 halves (16B) -> two float4 (f-quad, s-quad)
__device__ __forceinline__ void ldh8(const __half* p, float4& f, float4& s) {
    uint4 u = *reinterpret_cast<const uint4*>(p);
    __half2 h0 = *reinterpret_cast<__half2*>(&u.x);
    __half2 h1 = *reinterpret_cast<__half2*>(&u.y);
    __half2 h2 = *reinterpret_cast<__half2*>(&u.z);
    __half2 h3 = *reinterpret_cast<__half2*>(&u.w);
    float2 a = __half22float2(h0), b = __half22float2(h1);
    float2 c = __half22float2(h2), d = __half22float2(h3);
    f = make_float4(a.x, a.y, b.x, b.y);
    s = make_float4(c.x, c.y, d.x, d.y);
}

// ---------------- kernel 1: init ----------------
__global__ void k_init(const float* __restrict__ x) {
    int i = blockIdx.x * blockDim.x + threadIdx.x;
    if (i < N_NODES * NODE_DIMV) g_h1[i] = x[i];
    if (i < N_GRAPHS * HID) g_gsum[i] = 0.0f;
    if (i < N_GRAPHS) g_cnt[i] = 0.0f;
    if (i < N_NODES) { g_hist[i] = 0; g_fill[i] = 0; }
}

// ---------------- kernel 2: conv1 edges + dst histogram ----------------
__global__ void __launch_bounds__(256) k_conv1(
    const float* __restrict__ x, const float* __restrict__ ea,
    const int* __restrict__ src, const int* __restrict__ dst,
    const float* __restrict__ W1f, const float* __restrict__ b1f,
    const float* __restrict__ W1s, const float* __restrict__ b1s)
{
    __shared__ float swf[38 * 3], sws[38 * 3], sbf[3], sbs[3];
    int t = threadIdx.x;
    if (t < 114) { swf[t] = W1f[t]; sws[t] = W1s[t]; }
    if (t < 3)   { sbf[t] = b1f[t]; sbs[t] = b1s[t]; }
    __syncthreads();

    int e = blockIdx.x * blockDim.x + t;
    if (e >= N_EDGES) return;
    int s = src[e], d = dst[e];
    atomicAdd(&g_hist[d], 1);

    float xd[3], xs[3];
#pragma unroll
    for (int i = 0; i < 3; i++) { xd[i] = x[d * 3 + i]; xs[i] = x[s * 3 + i]; }

    float el[32];
    const float4* er = reinterpret_cast<const float4*>(ea + (size_t)e * 32);
#pragma unroll
    for (int q = 0; q < 8; q++) reinterpret_cast<float4*>(el)[q] = er[q];

#pragma unroll
    for (int c = 0; c < 3; c++) {
        float vf = sbf[c], vs = sbs[c];
#pragma unroll
        for (int i = 0; i < 3; i++) {
            vf += xd[i] * swf[i * 3 + c];        vs += xd[i] * sws[i * 3 + c];
            vf += xs[i] * swf[(3 + i) * 3 + c];  vs += xs[i] * sws[(3 + i) * 3 + c];
        }
#pragma unroll
        for (int k = 0; k < 32; k++) {
            vf += el[k] * swf[(6 + k) * 3 + c];
            vs += el[k] * sws[(6 + k) * 3 + c];
        }
        float m = sigf(vf) * spf(vs);
        atomicAdd(&g_h1[d * 3 + c], m);
    }
}

// ---------------- kernel 3: fused scatter + materialize ----------------
__global__ void __launch_bounds__(256) k_sortmat(
    const float* __restrict__ ea, const int* __restrict__ src, const int* __restrict__ dst)
{
    int t = threadIdx.x;
    int e = blockIdx.x * 64 + (t >> 2);
    int q = t & 3;
    int lane = t & 31;

    int d = dst[e];
    int pos = 0;
    if (q == 0) pos = g_off[d] + atomicAdd(&g_fill[d], 1);
    pos = __shfl_sync(0xffffffffu, pos, lane & ~3);
    if (q == 0) { g_dsts[pos] = d; g_srcs[pos] = src[e]; }

    const float4* sp = reinterpret_cast<const float4*>(ea + (size_t)e * 32) + q * 2;
    float4 v0 = sp[0], v1 = sp[1];
    union { uint4 u; __half2 h2[4]; } o;
    o.h2[0] = __floats2half2_rn(v0.x, v0.y);
    o.h2[1] = __floats2half2_rn(v0.z, v0.w);
    o.h2[2] = __floats2half2_rn(v1.x, v1.y);
    o.h2[3] = __floats2half2_rn(v1.z, v1.w);
    reinterpret_cast<uint4*>(g_eas + (size_t)pos * 32)[q] = o.u;
}

// ---------------- node pre-projection GEMM (tf32 mma) -> g_P (fp16, interleaved) ----
// grid (392, 4). Block (391, 0) runs the histogram exclusive scan instead (folded
// k_scan); blocks (391, y>0) exit. Others: slab bn = blockIdx.y.
__global__ void __launch_bounds__(256, 2) k_gemm_node(
    const float* __restrict__ Wf, const float* __restrict__ Ws, int amode,
    const float* __restrict__ Wp, const float* __restrict__ bp)
{
    __shared__ uint32_t As[128][32];
    __shared__ uint32_t Bs[128][32];

    int t = threadIdx.x;

    if (blockIdx.x == 391) {
        if (blockIdx.y == 0) {
            // 256-thread exclusive scan of g_hist -> g_off
            int* ssc = reinterpret_cast<int*>(As);
            const int CH = (N_NODES + 255) / 256;   // 196
            int lo = t * CH;
            int hi = lo + CH; if (hi > N_NODES) hi = N_NODES;
            int sum = 0;
            for (int i = lo; i < hi; i++) sum += g_hist[i];
            ssc[t] = sum;
            __syncthreads();
            for (int o = 1; o < 256; o <<= 1) {
                int xv = (t >= o) ? ssc[t - o] : 0;
                __syncthreads();
                ssc[t] += xv;
                __syncthreads();
            }
            int run = ssc[t] - sum;
            for (int i = lo; i < hi; i++) {
                int cc = g_hist[i];
                g_off[i] = run;
                run += cc;
            }
        }
        return;
    }

    int m0 = blockIdx.x * 128;
    int bn = blockIdx.y;
    const float* W = (bn & 1) ? Ws : Wf;
    int krow0 = (bn >> 1) * 128;

    int lane = t & 31, warp = t >> 5;
    int gid = lane >> 2, tig = lane & 3;
    int wm = warp >> 1, wn = warp & 1;

    float c[2][8][4] = {};

    for (int kc = 0; kc < 4; kc++) {
#pragma unroll
        for (int i = 0; i < 16; i++) {
            int idx = t + i * 256;
            int m = idx >> 5, k = idx & 31;
            int row = m0 + m;
            int cc = kc * 32 + k;
            float v = 0.0f;
            if (row < N_NODES) {
                if (amode == 2) {
                    float a = g_h1[row * 3], b = g_h1[row * 3 + 1], d = g_h1[row * 3 + 2];
                    v = fmaxf(bp[cc] + a * Wp[cc] + b * Wp[128 + cc] + d * Wp[256 + cc], 0.0f);
                    if (bn == 0) g_acc2[(size_t)row * HID + cc] = v;
                } else {
                    v = fmaxf(g_acc2[(size_t)row * HID + cc], 0.0f);
                    if (bn == 0) g_acc3[(size_t)row * HID + cc] = v;
                }
            }
            As[m][k ^ ((m & 7) << 2)] = to_tf32(v);
        }
#pragma unroll
        for (int i = 0; i < 16; i++) {
            int idx = t + i * 256;
            int k = idx >> 7, n = idx & 127;
            float v = W[(size_t)(krow0 + kc * 32 + k) * HID + n];
            Bs[n][k ^ ((n & 7) << 2)] = to_tf32(v);
        }
        __syncthreads();

#pragma unroll
        for (int ks = 0; ks < 4; ks++) {
            int k0 = ks * 8;
            uint32_t a[2][4];
#pragma unroll
            for (int mt = 0; mt < 2; mt++) {
                int m = wm * 32 + mt * 16 + gid;
                int sw = (m & 7) << 2;
                a[mt][0] = As[m][(k0 + tig) ^ sw];
                a[mt][1] = As[m + 8][(k0 + tig) ^ sw];
                a[mt][2] = As[m][(k0 + tig + 4) ^ sw];
                a[mt][3] = As[m + 8][(k0 + tig + 4) ^ sw];
            }
#pragma unroll
            for (int nt = 0; nt < 8; nt++) {
                int n = wn * 64 + nt * 8 + gid;
                int sw = (n & 7) << 2;
                uint32_t b[2] = { Bs[n][(k0 + tig) ^ sw], Bs[n][(k0 + tig + 4) ^ sw] };
                mma_tf32(c[0][nt], a[0], b);
                mma_tf32(c[1][nt], a[1], b);
            }
        }
        __syncthreads();
    }

    // epilogue: quad-interleaved fp16 store.
    // part = bn (0:fd, 1:sd, 2:fs, 3:ss); channel ch -> offset:
    //   (part>=2 ? 256:0) + (ch>>2)*8 + (ch&3) + (part&1 ? 4:0)
    int rb = m0 + wm * 32;
    int pbase = (bn >= 2 ? 256 : 0) + ((bn & 1) ? 4 : 0);
#pragma unroll
    for (int mt = 0; mt < 2; mt++) {
#pragma unroll
        for (int nt = 0; nt < 8; nt++) {
            int r0 = rb + mt * 16 + gid;
            int ch = wn * 64 + nt * 8 + 2 * tig;
            int off = pbase + (ch >> 2) * 8 + (ch & 3);
            if (r0 < N_NODES)
                *reinterpret_cast<__half2*>(g_P + (size_t)r0 * 512 + off) =
                    __floats2half2_rn(c[mt][nt][0], c[mt][nt][1]);
            int r1 = r0 + 8;
            if (r1 < N_NODES)
                *reinterpret_cast<__half2*>(g_P + (size_t)r1 * 512 + off) =
                    __floats2half2_rn(c[mt][nt][2], c[mt][nt][3]);
        }
    }
}

// ---------------- fused conv edge kernel (fp16 HMMA, sorted, streamed) ----------------
// One block = 64 sorted edges. Edge phase now does 2 LDG.128 per edge (interleaved g_P)
// instead of 4 LDG.64.
__global__ void __launch_bounds__(256, 3) k_fused4(
    const float* __restrict__ Wef, const float* __restrict__ Wes,
    const float* __restrict__ bf, const float* __restrict__ bs, int mode)
{
    __shared__ __align__(16) char sbuf[25600];
    __shared__ __align__(16) __half smf[64][132];
    __shared__ float sbf[128], sbs[128];
    __shared__ int sdst[64], ssrc[64];

    __half (*As)[40]  = reinterpret_cast<__half(*)[40]>(sbuf);
    __half (*Bs)[40]  = reinterpret_cast<__half(*)[40]>(sbuf + 5120);
    __half (*sms)[132] = reinterpret_cast<__half(*)[132]>(sbuf);

    float* acc = (mode == 0) ? g_acc2 : g_acc3;
    int t = threadIdx.x;
    int e0 = blockIdx.x * 64;

    if (t < 128) sbf[t] = bf[t];
    else         sbs[t - 128] = bs[t - 128];
    if (t < 64) { sdst[t] = g_dsts[e0 + t]; ssrc[t] = g_srcs[e0 + t]; }

    // stage A: sorted fp16 edge attrs [64 x 32]
    {
        int r = t >> 2, q = t & 3;
        const uint4* sp = reinterpret_cast<const uint4*>(g_eas + (size_t)(e0 + r) * 32);
        *reinterpret_cast<uint4*>(&As[r][q * 8]) = sp[q];
    }
    // stage B: both weight halves [256 x 32] fp16 (rows 0-127 = f, 128-255 = s)
    {
        int n = t, nn = t & 127;
        const float* W = (n < 128) ? Wef : Wes;
#pragma unroll
        for (int i = 0; i < 16; i++) {
            int k2 = i * 2;
            *reinterpret_cast<__half2*>(&Bs[n][k2]) =
                __floats2half2_rn(W[k2 * 128 + nn], W[(k2 + 1) * 128 + nn]);
        }
    }
    __syncthreads();

    int lane = t & 31, warp = t >> 5;
    int gid = lane >> 2, tig = lane & 3;
    int wm = warp >> 2, wn = warp & 3;

    float c[2][4][4];

    // ---- GEMM f-half ----
#pragma unroll
    for (int mt = 0; mt < 2; mt++)
#pragma unroll
        for (int nt = 0; nt < 4; nt++)
#pragma unroll
            for (int p = 0; p < 4; p++) c[mt][nt][p] = 0.0f;

#pragma unroll
    for (int ks = 0; ks < 2; ks++) {
        int k0 = ks * 16;
        uint32_t a[2][4];
#pragma unroll
        for (int mt = 0; mt < 2; mt++) {
            int m = wm * 32 + mt * 16 + gid;
            a[mt][0] = *reinterpret_cast<const uint32_t*>(&As[m][k0 + tig * 2]);
            a[mt][1] = *reinterpret_cast<const uint32_t*>(&As[m + 8][k0 + tig * 2]);
            a[mt][2] = *reinterpret_cast<const uint32_t*>(&As[m][k0 + 8 + tig * 2]);
            a[mt][3] = *reinterpret_cast<const uint32_t*>(&As[m + 8][k0 + 8 + tig * 2]);
        }
#pragma unroll
        for (int nt = 0; nt < 4; nt++) {
            int n = wn * 32 + nt * 8 + gid;
            uint32_t b[2] = {
                *reinterpret_cast<const uint32_t*>(&Bs[n][k0 + tig * 2]),
                *reinterpret_cast<const uint32_t*>(&Bs[n][k0 + 8 + tig * 2]) };
            mma_f16(c[0][nt], a[0], b);
            mma_f16(c[1][nt], a[1], b);
        }
    }
#pragma unroll
    for (int mt = 0; mt < 2; mt++) {
#pragma unroll
        for (int nt = 0; nt < 4; nt++) {
            int r = wm * 32 + mt * 16 + gid;
            int cc = wn * 32 + nt * 8 + 2 * tig;
            *reinterpret_cast<__half2*>(&smf[r][cc]) =
                __floats2half2_rn(c[mt][nt][0], c[mt][nt][1]);
            *reinterpret_cast<__half2*>(&smf[r + 8][cc]) =
                __floats2half2_rn(c[mt][nt][2], c[mt][nt][3]);
        }
    }

    // ---- GEMM s-half ----
#pragma unroll
    for (int mt = 0; mt < 2; mt++)
#pragma unroll
        for (int nt = 0; nt < 4; nt++)
#pragma unroll
            for (int p = 0; p < 4; p++) c[mt][nt][p] = 0.0f;

#pragma unroll
    for (int ks = 0; ks < 2; ks++) {
        int k0 = ks * 16;
        uint32_t a[2][4];
#pragma unroll
        for (int mt = 0; mt < 2; mt++) {
            int m = wm * 32 + mt * 16 + gid;
            a[mt][0] = *reinterpret_cast<const uint32_t*>(&As[m][k0 + tig * 2]);
            a[mt][1] = *reinterpret_cast<const uint32_t*>(&As[m + 8][k0 + tig * 2]);
            a[mt][2] = *reinterpret_cast<const uint32_t*>(&As[m][k0 + 8 + tig * 2]);
            a[mt][3] = *reinterpret_cast<const uint32_t*>(&As[m + 8][k0 + 8 + tig * 2]);
        }
#pragma unroll
        for (int nt = 0; nt < 4; nt++) {
            int n = 128 + wn * 32 + nt * 8 + gid;
            uint32_t b[2] = {
                *reinterpret_cast<const uint32_t*>(&Bs[n][k0 + tig * 2]),
                *reinterpret_cast<const uint32_t*>(&Bs[n][k0 + 8 + tig * 2]) };
            mma_f16(c[0][nt], a[0], b);
            mma_f16(c[1][nt], a[1], b);
        }
    }
    __syncthreads();   // done reading As/Bs — safe to alias with sms

#pragma unroll
    for (int mt = 0; mt < 2; mt++) {
#pragma unroll
        for (int nt = 0; nt < 4; nt++) {
            int r = wm * 32 + mt * 16 + gid;
            int cc = wn * 32 + nt * 8 + 2 * tig;
            *reinterpret_cast<__half2*>(&sms[r][cc]) =
                __floats2half2_rn(c[mt][nt][0], c[mt][nt][1]);
            *reinterpret_cast<__half2*>(&sms[r + 8][cc]) =
                __floats2half2_rn(c[mt][nt][2], c[mt][nt][3]);
        }
    }
    __syncthreads();

    // ---- edge phase: 8 edges per warp, 2 LDG.128 gathers per edge ----
    int c0 = lane * 4;
    int po = lane * 8;   // interleaved offset within part
    const float4 bfv = *reinterpret_cast<const float4*>(&sbf[c0]);
    const float4 bsv = *reinterpret_cast<const float4*>(&sbs[c0]);
    int base = warp * 8;

    float4 mv[8];
#pragma unroll
    for (int j = 0; j < 8; j++) {
        int el = base + j;
        int d = sdst[el], s = ssrc[el];

        float4 ef = ldh4(&smf[el][c0]);
        float4 es = ldh4(&sms[el][c0]);
        float4 fd, sd, fs, ss;
        ldh8(g_P + (size_t)d * 512 + po, fd, sd);        // dst part (L1 hit within run)
        ldh8(g_P + (size_t)s * 512 + 256 + po, fs, ss);  // src part

        float vf0 = ef.x + fd.x + fs.x + bfv.x;
        float vf1 = ef.y + fd.y + fs.y + bfv.y;
        float vf2 = ef.z + fd.z + fs.z + bfv.z;
        float vf3 = ef.w + fd.w + fs.w + bfv.w;
        float vs0 = es.x + sd.x + ss.x + bsv.x;
        float vs1 = es.y + sd.y + ss.y + bsv.y;
        float vs2 = es.z + sd.z + ss.z + bsv.z;
        float vs3 = es.w + sd.w + ss.w + bsv.w;

        mv[j].x = sigf(vf0) * spf(vs0);
        mv[j].y = sigf(vf1) * spf(vs1);
        mv[j].z = sigf(vf2) * spf(vs2);
        mv[j].w = sigf(vf3) * spf(vs3);
    }

    float a0 = 0.f, a1 = 0.f, a2 = 0.f, a3 = 0.f;
#pragma unroll
    for (int j = 0; j < 8; j++) {
        a0 += mv[j].x; a1 += mv[j].y; a2 += mv[j].z; a3 += mv[j].w;
        int d = sdst[base + j];
        bool flush = (j == 7) || (sdst[base + j + 1] != d);
        if (flush) {
            red4(acc + (size_t)d * 128 + c0, a0, a1, a2, a3);
            a0 = a1 = a2 = a3 = 0.f;
        }
    }
}

// ---------------- pooling ----------------
__global__ void k_pool(const int* __restrict__ batch) {
    int i = blockIdx.x * blockDim.x + threadIdx.x;
    if (i >= N_NODES * 32) return;
    int n = i >> 5, q = i & 31;
    int b = batch[n];
    float4 v = *reinterpret_cast<const float4*>(&g_acc3[(size_t)n * 128 + q * 4]);
    v.x = fmaxf(v.x, 0.f); v.y = fmaxf(v.y, 0.f);
    v.z = fmaxf(v.z, 0.f); v.w = fmaxf(v.w, 0.f);
    red4(&g_gsum[(size_t)b * 128 + q * 4], v.x, v.y, v.z, v.w);
    if (q == 0) atomicAdd(&g_cnt[b], 1.0f);
}

// ---------------- head MLP ----------------
__global__ void __launch_bounds__(128) k_head(
    const float* __restrict__ Wfc, const float* __restrict__ bfc,
    const float* __restrict__ Wh, const float* __restrict__ bh,
    float* __restrict__ out)
{
    __shared__ float sg[128], sh[128];
    int b = blockIdx.x, t = threadIdx.x;
    float cnt = fmaxf(g_cnt[b], 1.0f);
    sg[t] = g_gsum[(size_t)b * 128 + t] / cnt;
    __syncthreads();
    float a = bfc[t];
#pragma unroll 8
    for (int k = 0; k < 128; k++) a += sg[k] * Wfc[k * 128 + t];
    sh[t] = fmaxf(a, 0.0f);
    __syncthreads();
    if (t < N_HEADSV) {
        float a2 = bh[t];
#pragma unroll 8
        for (int k = 0; k < 128; k++) a2 += sh[k] * Wh[k * 5 + t];
        out[b * 5 + t] = a2;
    }
}

// ---------------- launch ----------------
extern "C" void kernel_launch(void* const* d_in, const int* in_sizes, int n_in,
                              void* d_out, int out_size) {
    (void)in_sizes; (void)n_in; (void)out_size;
    const float* x    = (const float*)d_in[0];
    const float* ea   = (const float*)d_in[1];
    const int*   ei   = (const int*)d_in[2];
    const int*   batch= (const int*)d_in[3];
    const float* W1f  = (const float*)d_in[4];
    const float* b1f  = (const float*)d_in[5];
    const float* W1s  = (const float*)d_in[6];
    const float* b1s  = (const float*)d_in[7];
    const float* Wp   = (const float*)d_in[8];
    const float* bp   = (const float*)d_in[9];
    const float* W2f  = (const float*)d_in[10];
    const float* b2f  = (const float*)d_in[11];
    const float* W2s  = (const float*)d_in[12];
    const float* b2s  = (const float*)d_in[13];
    const float* W3f  = (const float*)d_in[14];
    const float* b3f  = (const float*)d_in[15];
    const float* W3s  = (const float*)d_in[16];
    const float* b3s  = (const float*)d_in[17];
    const float* Wfc  = (const float*)d_in[18];
    const float* bfc  = (const float*)d_in[19];
    const float* Wh   = (const float*)d_in[20];
    const float* bh   = (const float*)d_in[21];
    const int* src = ei;
    const int* dst = ei + N_EDGES;
    float* out = (float*)d_out;

    // 1) init
    k_init<<<(N_NODES * NODE_DIMV + 255) / 256, 256>>>(x);
    // 2) conv1 + dst histogram
    k_conv1<<<(N_EDGES + 255) / 256, 256>>>(x, ea, src, dst, W1f, b1f, W1s, b1s);
    // 3) conv2 node proj GEMM + folded histogram scan (block 391,0)
    k_gemm_node<<<dim3(392, 4), 256>>>(W2f, W2s, 2, Wp, bp);
    // 4) scatter + materialize sorted fp16 edge data (needs g_off from scan)
    k_sortmat<<<N_EDGES / 64, 256>>>(ea, src, dst);
    // 5) conv2 fused edge pass  (user-kernel index 4 — target profile slot)
    k_fused4<<<N_EDGES / 64, 256>>>(W2f + 256 * 128, W2s + 256 * 128, b2f, b2s, 0);
    // 6) conv3 node proj GEMM (scan block re-runs harmlessly)
    k_gemm_node<<<dim3(392, 4), 256>>>(W3f, W3s, 1, Wp, bp);
    // 7) conv3 fused edge pass
    k_fused4<<<N_EDGES / 64, 256>>>(W3f + 256 * 128, W3s + 256 * 128, b3f, b3s, 1);
    // 8) pooling + head
    k_pool<<<(N_NODES * 32 + 255) / 256, 256>>>(batch);
    k_head<<<N_GRAPHS, 128>>>(Wfc, bfc, Wh, bh, out);
}